// round 3
// baseline (speedup 1.0000x reference)
#include <cuda_runtime.h>
#include <math.h>

#define TILE 32
#define BROWS 8   // blockDim.y; each thread covers TILE/BROWS = 4 rows

// Uncompress packed strict-upper-triangle vector into full symmetric matrix
// with unit diagonal.
//
// comp layout (row-major strict upper triangle):
//   idx(i,j) = i*(n-1) - i*(i-1)/2 + (j - i - 1),   for j > i
//
// Grid: (n/TILE, n/TILE). Block (bj, bi):
//   bj <  bi : return (mirror handled by the (bi, bj) block)
//   bj == bi : diagonal tile — mirror within tile, ones on diagonal
//   bj >  bi : load upper tile coalesced, write it, transpose via smem,
//              write mirror tile coalesced.
__global__ void uncompress_sym_kernel(const float* __restrict__ comp,
                                      float* __restrict__ out,
                                      int n) {
    const int bi = blockIdx.y;
    const int bj = blockIdx.x;
    if (bj < bi) return;

    __shared__ float s[TILE][TILE + 1];

    const int tx = threadIdx.x;           // 0..31 -> column within tile
    const int ty = threadIdx.y;           // 0..7
    const int i0 = bi * TILE;
    const int j0 = bj * TILE;

    if (bi == bj) {
        // Diagonal tile: load strict-upper part into smem.
        #pragma unroll
        for (int r = ty; r < TILE; r += BROWS) {
            const int i = i0 + r;
            const int j = j0 + tx;
            float v = 0.0f;
            if (j > i) {
                const int idx = i * (n - 1) - (i * (i - 1)) / 2 + (j - i - 1);
                v = comp[idx];
            }
            s[r][tx] = v;
        }
        __syncthreads();
        #pragma unroll
        for (int r = ty; r < TILE; r += BROWS) {
            const int i = i0 + r;
            const int j = j0 + tx;
            float v;
            if (tx > r)       v = s[r][tx];       // upper
            else if (tx == r) v = 1.0f;           // diagonal
            else              v = s[tx][r];       // lower = mirror
            out[(size_t)i * n + j] = v;
        }
    } else {
        // Off-diagonal upper tile: fully inside strict upper triangle.
        #pragma unroll
        for (int r = ty; r < TILE; r += BROWS) {
            const int i = i0 + r;
            const int j = j0 + tx;
            const int idx = i * (n - 1) - (i * (i - 1)) / 2 + (j - i - 1);
            const float v = comp[idx];            // coalesced: contiguous in j
            s[r][tx] = v;
            out[(size_t)i * n + j] = v;           // coalesced write, upper tile
        }
        __syncthreads();
        // Mirror tile: out[j][i] = tile^T, read smem transposed (padded, no
        // bank conflicts), write coalesced.
        #pragma unroll
        for (int r = ty; r < TILE; r += BROWS) {
            const int i = j0 + r;                 // row in the mirror tile
            const int j = i0 + tx;
            out[(size_t)i * n + j] = s[tx][r];
        }
    }
}

extern "C" void kernel_launch(void* const* d_in, const int* in_sizes, int n_in,
                              void* d_out, int out_size) {
    const float* comp = (const float*)d_in[0];
    float* out = (float*)d_out;

    // m = n*(n-1)/2  ->  n = round(sqrt(2m)) + 1
    // MUST be computed in double: for m = 33550336, sqrt(2m) = 8191.4999847,
    // which rounds to exactly 8191.5 in fp32 -> llroundf gives 8192 -> n=8193
    // (off by one, OOB). In double it correctly gives 8191 -> n = 8192.
    const long long m = (long long)in_sizes[0];
    const int n = (int)llround(sqrt(2.0 * (double)m)) + 1;  // 8192

    dim3 block(TILE, BROWS);
    dim3 grid(n / TILE, n / TILE);
    uncompress_sym_kernel<<<grid, block>>>(comp, out, n);
}

// round 4
// speedup vs baseline: 1.3338x; 1.3338x over previous
#include <cuda_runtime.h>
#include <math.h>

#define T 64
#define THREADS 256
#define PITCH 65   // +1 float pad: transpose-phase LDS at worst 2-way conflicted

// Uncompress packed strict-upper-triangle vector (row-major, j>i) into a full
// symmetric n x n matrix with unit diagonal.
//   idx(i,j) = i*(n-1) - i*(i-1)/2 + (j - i - 1)
//
// Triangular grid: one block per upper-triangle 64x64 tile (bj >= bi).
// Off-diagonal block: load comp coalesced -> write upper tile (from regs) +
// stash in smem -> transpose -> float4-write the mirror tile.
__global__ void __launch_bounds__(THREADS)
uncompress_sym_kernel(const float* __restrict__ comp,
                      float* __restrict__ out,
                      int n, int nb) {
    __shared__ float s[T * PITCH];

    // Linear block id -> (bi, bj) in the upper triangle (row-major, incl diag).
    // start(bi) = bi*(2*nb - bi + 1)/2
    const int t = blockIdx.x;
    const float ff = (float)nb + 0.5f;
    int bi = (int)(ff - sqrtf(fmaxf(ff * ff - 2.0f * (float)t, 0.0f)));
    if (bi > nb - 1) bi = nb - 1;
    if (bi < 0) bi = 0;
    while (bi + 1 <= nb - 1 && ((bi + 1) * (2 * nb - bi)) / 2 <= t) bi++;
    while (bi > 0 && (bi * (2 * nb - bi + 1)) / 2 > t) bi--;
    const int bj = bi + (t - (bi * (2 * nb - bi + 1)) / 2);

    const int i0 = bi * T;
    const int j0 = bj * T;
    const int tid = threadIdx.x;

    if (bi != bj) {
        // Phase 1: coalesced load from comp, direct upper-tile store, smem stash.
        // 16 iterations; per iter the 256 threads cover 4 full 64-float rows.
        #pragma unroll
        for (int it = 0; it < (T * T) / THREADS; it++) {
            const int idx = it * THREADS + tid;
            const int r = idx >> 6;       // row within tile
            const int c = idx & 63;       // col within tile
            const int i = i0 + r;
            const int j = j0 + c;
            const int ci = i * (n - 1) - ((i * (i - 1)) >> 1) + (j - i - 1);
            const float v = comp[ci];                 // coalesced (contig in j)
            s[r * PITCH + c] = v;
            out[(size_t)i * n + j] = v;               // coalesced 128B/warp
        }
        __syncthreads();
        // Phase 2: mirror tile out[j][i] = tile^T, float4 stores (16B aligned:
        // i0 is a multiple of 64).
        #pragma unroll
        for (int it = 0; it < (T * T) / (THREADS * 4); it++) {
            const int idx = it * THREADS + tid;
            const int r  = idx >> 4;            // row within mirror tile (0..63)
            const int c4 = (idx & 15) << 2;     // starting col (multiple of 4)
            float4 v;
            v.x = s[(c4 + 0) * PITCH + r];
            v.y = s[(c4 + 1) * PITCH + r];
            v.z = s[(c4 + 2) * PITCH + r];
            v.w = s[(c4 + 3) * PITCH + r];
            *(float4*)&out[(size_t)(j0 + r) * n + (i0 + c4)] = v;
        }
    } else {
        // Diagonal tile (128 of 8256 blocks): load strict upper, mirror in smem.
        #pragma unroll
        for (int it = 0; it < (T * T) / THREADS; it++) {
            const int idx = it * THREADS + tid;
            const int r = idx >> 6;
            const int c = idx & 63;
            const int i = i0 + r;
            const int j = j0 + c;
            float v = 0.0f;
            if (j > i) {
                const int ci = i * (n - 1) - ((i * (i - 1)) >> 1) + (j - i - 1);
                v = comp[ci];
            }
            s[r * PITCH + c] = v;
        }
        __syncthreads();
        #pragma unroll
        for (int it = 0; it < (T * T) / THREADS; it++) {
            const int idx = it * THREADS + tid;
            const int r = idx >> 6;
            const int c = idx & 63;
            float v;
            if (c > r)       v = s[r * PITCH + c];
            else if (c == r) v = 1.0f;
            else             v = s[c * PITCH + r];
            out[(size_t)(i0 + r) * n + (j0 + c)] = v;
        }
    }
}

extern "C" void kernel_launch(void* const* d_in, const int* in_sizes, int n_in,
                              void* d_out, int out_size) {
    const float* comp = (const float*)d_in[0];
    float* out = (float*)d_out;

    // n = round(sqrt(2m)) + 1 — MUST be double: sqrt(2*33550336) = 8191.49998,
    // which rounds to exactly 8191.5 in fp32 and would give n=8193 (OOB).
    const long long m = (long long)in_sizes[0];
    const int n = (int)llround(sqrt(2.0 * (double)m)) + 1;  // 8192
    const int nb = n / T;                                   // 128

    const int nblocks = nb * (nb + 1) / 2;                  // 8256
    uncompress_sym_kernel<<<nblocks, THREADS>>>(comp, out, n, nb);
}

// round 5
// speedup vs baseline: 1.3937x; 1.0449x over previous
#include <cuda_runtime.h>
#include <math.h>

#define T 64
#define THREADS 256
#define PITCH 65   // +1 float pad; all smem access is scalar, odd pitch safe

// Uncompress packed strict-upper-triangle vector (row-major, j>i) into a full
// symmetric n x n matrix with unit diagonal.
//   idx(i,j) = i*(n-1) - i*(i-1)/2 + (j - i - 1)
//
// Triangular grid: one block per upper-triangle 64x64 tile (bj >= bi).
// Off-diagonal block: load comp coalesced -> write upper tile (from regs) +
// stash in smem -> transpose -> float4-write the mirror tile.
// __launch_bounds__(256, 6): cap regs ~42 so 6 blocks/SM (48 warps, 75% occ)
// — R4 showed regs=64 -> 4 blocks -> 47% occ was starving chip-wide MLP.
__global__ void __launch_bounds__(THREADS, 6)
uncompress_sym_kernel(const float* __restrict__ comp,
                      float* __restrict__ out,
                      int n, int nb) {
    __shared__ float s[T * PITCH];

    // Linear block id -> (bi, bj) in the upper triangle (row-major, incl diag).
    // start(bi) = bi*(2*nb - bi + 1)/2
    const int t = blockIdx.x;
    const float ff = (float)nb + 0.5f;
    int bi = (int)(ff - sqrtf(fmaxf(ff * ff - 2.0f * (float)t, 0.0f)));
    if (bi > nb - 1) bi = nb - 1;
    if (bi < 0) bi = 0;
    while (bi + 1 <= nb - 1 && ((bi + 1) * (2 * nb - bi)) / 2 <= t) bi++;
    while (bi > 0 && (bi * (2 * nb - bi + 1)) / 2 > t) bi--;
    const int bj = bi + (t - (bi * (2 * nb - bi + 1)) / 2);

    const int i0 = bi * T;
    const int j0 = bj * T;
    const int tid = threadIdx.x;

    if (bi != bj) {
        // Phase 1: coalesced load from comp, direct upper-tile store, smem stash.
        #pragma unroll
        for (int it = 0; it < (T * T) / THREADS; it++) {
            const int idx = it * THREADS + tid;
            const int r = idx >> 6;       // row within tile
            const int c = idx & 63;       // col within tile
            const int i = i0 + r;
            const int j = j0 + c;
            const int ci = i * (n - 1) - ((i * (i - 1)) >> 1) + (j - i - 1);
            const float v = comp[ci];                 // coalesced (contig in j)
            s[r * PITCH + c] = v;
            out[(size_t)i * n + j] = v;               // coalesced 128B/warp
        }
        __syncthreads();
        // Phase 2: mirror tile out[j][i] = tile^T, float4 stores (16B aligned:
        // i0 is a multiple of 64).
        #pragma unroll
        for (int it = 0; it < (T * T) / (THREADS * 4); it++) {
            const int idx = it * THREADS + tid;
            const int r  = idx >> 4;            // row within mirror tile (0..63)
            const int c4 = (idx & 15) << 2;     // starting col (multiple of 4)
            float4 v;
            v.x = s[(c4 + 0) * PITCH + r];
            v.y = s[(c4 + 1) * PITCH + r];
            v.z = s[(c4 + 2) * PITCH + r];
            v.w = s[(c4 + 3) * PITCH + r];
            *(float4*)&out[(size_t)(j0 + r) * n + (i0 + c4)] = v;
        }
    } else {
        // Diagonal tile (128 of 8256 blocks): load strict upper, mirror in smem.
        #pragma unroll
        for (int it = 0; it < (T * T) / THREADS; it++) {
            const int idx = it * THREADS + tid;
            const int r = idx >> 6;
            const int c = idx & 63;
            const int i = i0 + r;
            const int j = j0 + c;
            float v = 0.0f;
            if (j > i) {
                const int ci = i * (n - 1) - ((i * (i - 1)) >> 1) + (j - i - 1);
                v = comp[ci];
            }
            s[r * PITCH + c] = v;
        }
        __syncthreads();
        #pragma unroll
        for (int it = 0; it < (T * T) / THREADS; it++) {
            const int idx = it * THREADS + tid;
            const int r = idx >> 6;
            const int c = idx & 63;
            float v;
            if (c > r)       v = s[r * PITCH + c];
            else if (c == r) v = 1.0f;
            else             v = s[c * PITCH + r];
            out[(size_t)(i0 + r) * n + (j0 + c)] = v;
        }
    }
}

extern "C" void kernel_launch(void* const* d_in, const int* in_sizes, int n_in,
                              void* d_out, int out_size) {
    const float* comp = (const float*)d_in[0];
    float* out = (float*)d_out;

    // n = round(sqrt(2m)) + 1 — MUST be double: sqrt(2*33550336) = 8191.49998,
    // which rounds to exactly 8191.5 in fp32 and would give n=8193 (OOB).
    const long long m = (long long)in_sizes[0];
    const int n = (int)llround(sqrt(2.0 * (double)m)) + 1;  // 8192
    const int nb = n / T;                                   // 128

    const int nblocks = nb * (nb + 1) / 2;                  // 8256
    uncompress_sym_kernel<<<nblocks, THREADS>>>(comp, out, n, nb);
}